// round 5
// baseline (speedup 1.0000x reference)
#include <cuda_runtime.h>

// Fixed problem shapes.
#define Bb      8
#define CF      256
#define Hh      128
#define Ww      128
#define HL      512
#define WL      512
#define C_OLD   16
#define NPIX    (Bb * Hh * Ww)           // 131072
#define NSEG    (NPIX / 16)              // 8192 16-pixel row segments
#define P2BLK   608                      // phase-2 grid (4 * 152 SMs)
#define P2W     ((P2BLK * 256) / 32)     // 4864 warps

// Persistent scratch (no allocation). Zero at module load; k_final re-zeroes
// everything dirtied so each graph replay starts from identical state.
__device__ int            g_segcnt = 0;
__device__ int            g_seg[NSEG];
__device__ unsigned char  g_idmap[NPIX];
__device__ float          g_sum[16];
__device__ int            g_cnt[16];

// ---------------- Phase 1: label gather + conditional argmax + segment compaction ----
// One thread per downsampled pixel (512 blocks x 256). Warps cover 32
// consecutive, 32-aligned pixels -> full-mask ballot is safe; each 16-pixel
// segment is seen by exactly one half-warp.
__global__ void __launch_bounds__(256)
k_phase1(const int* __restrict__ labels,
         const float* __restrict__ outputs_old)
{
    __shared__ int s_cnt[16];
    int tid  = threadIdx.x;
    int lane = tid & 31;
    if (tid < 16) s_cnt[tid] = 0;
    __syncthreads();

    int pix = blockIdx.x * 256 + tid;
    int b = pix >> 14;
    int h = (pix >> 7) & 127;
    int w = pix & 127;

    int lab = labels[(b * HL + 4 * h) * WL + 4 * w];   // nearest-down: src = 4*dst
    int id = 0;
    if (lab == 0) {
        const float* p = outputs_old
                       + (size_t)b * C_OLD * HL * WL
                       + (size_t)(4 * h) * WL + 4 * w;
        float best = p[0];
        #pragma unroll
        for (int c = 1; c < C_OLD; ++c) {
            float v = p[(size_t)c * HL * WL];
            if (v > best) { best = v; id = c; }        // strict > = first-max (jnp.argmax)
        }
    }
    g_idmap[pix] = (unsigned char)id;
    if (id) atomicAdd(&s_cnt[id], 1);

    unsigned m = __ballot_sync(0xffffffffu, id != 0);
    if (lane == 0 && m) {
        unsigned lo = m & 0xffffu, hi = m >> 16;
        int n = (lo != 0) + (hi != 0);
        int base = atomicAdd(&g_segcnt, n);
        int sg = pix >> 4;
        if (lo) g_seg[base++] = sg;
        if (hi) g_seg[base]   = sg + 1;
    }

    __syncthreads();
    if (tid < 16 && s_cnt[tid]) atomicAdd(&g_cnt[tid], s_cnt[tid]);
}

// ---------------- Phase 2: warp per occupied 16-pixel segment ----------------
// Lanes 0-15 handle even channels, lanes 16-31 odd channels; each lane owns
// pixel (lane & 15). Loads predicated per-lane so only 32B sectors containing
// active pixels are fetched from DRAM.
__global__ void __launch_bounds__(256)
k_phase2(const float* __restrict__ features,
         const float* __restrict__ proto)
{
    __shared__ float s_proto[16 * 257];   // padded rows
    __shared__ float s_sum[16];
    int tid  = threadIdx.x;
    int lane = tid & 31;

    if (tid < 16) s_sum[tid] = 0.0f;
    for (int i = tid; i < 16 * CF; i += 256)
        s_proto[(i >> 8) * 257 + (i & 255)] = proto[i];
    __syncthreads();

    const int segcnt = g_segcnt;          // stream-ordered after phase 1
    const int gw = (blockIdx.x * 256 + tid) >> 5;
    for (int s = gw; s < segcnt; s += P2W) {
        int seg  = g_seg[s];
        int base = seg << 4;
        int b    = base >> 14;
        int hw0  = base & 16383;
        int j    = lane & 15;
        int coff = lane >> 4;             // 0 = even channels, 1 = odd

        int id = g_idmap[base + j];
        float acc = 0.0f;
        if (id != 0) {
            const float* f  = features + b * (CF * Hh * Ww) + coff * (Hh * Ww) + hw0 + j;
            const float* pp = s_proto + id * 257 + coff;
            #pragma unroll 8
            for (int c = 0; c < CF; c += 2) {
                float d = f[c * (Hh * Ww)] - pp[c];
                acc += d * d;
            }
        }
        acc += __shfl_xor_sync(0xffffffffu, acc, 16);  // combine channel halves
        if (lane < 16 && id != 0)
            atomicAdd(&s_sum[id], acc * (1.0f / CF));
    }
    __syncthreads();
    if (tid < 16 && s_sum[tid] != 0.0f) atomicAdd(&g_sum[tid], s_sum[tid]);
}

// ---------------- Finalize (lane-parallel) + scratch reset ----------------
__global__ void k_final(const int* __restrict__ classes_old,
                        const int* __restrict__ inc_step,
                        float* __restrict__ out)
{
    int lane = threadIdx.x;
    int nc = *classes_old;
    if (nc > 16) nc = 16;
    float v = 0.0f;
    if (lane >= 1 && lane < nc && g_cnt[lane] > 0)
        v = g_sum[lane] / (float)g_cnt[lane];
    #pragma unroll
    for (int o = 16; o; o >>= 1)
        v += __shfl_xor_sync(0xffffffffu, v, o);
    if (lane == 0)
        out[0] = (*inc_step == 0) ? 0.0f : v;
    // reset scratch for the next graph replay
    if (lane == 0) g_segcnt = 0;
    if (lane < 16) { g_sum[lane] = 0.0f; g_cnt[lane] = 0; }
}

extern "C" void kernel_launch(void* const* d_in, const int* in_sizes, int n_in,
                              void* d_out, int out_size) {
    // metadata order:
    // 0: outputs (unused)        1: outputs_old f32 [8,16,512,512]
    // 2: features f32 [8,256,128,128]   3: features_old (unused)
    // 4: labels i32 [8,512,512]  5: prototypes f32 [21,256]
    // 6: classes_old i32         7: incremental_step i32
    const float* outputs_old = (const float*)d_in[1];
    const float* features    = (const float*)d_in[2];
    const int*   labels      = (const int*)  d_in[4];
    const float* prototypes  = (const float*)d_in[5];
    const int*   classes_old = (const int*)  d_in[6];
    const int*   inc_step    = (const int*)  d_in[7];

    k_phase1<<<NPIX / 256, 256>>>(labels, outputs_old);
    k_phase2<<<P2BLK, 256>>>(features, prototypes);
    k_final<<<1, 32>>>(classes_old, inc_step, (float*)d_out);
}

// round 9
// speedup vs baseline: 1.4184x; 1.4184x over previous
#include <cuda_runtime.h>

// Fixed problem shapes.
#define Bb      8
#define CF      256
#define Hh      128
#define Ww      128
#define HL      512
#define WL      512
#define C_OLD   16
#define HW      (Hh * Ww)                 // 16384
#define NPIX    (Bb * HW)                 // 131072
#define NBLK    (NPIX / 256)              // 512 blocks, 256 pixels each
#define NTHR    256

// Persistent scratch (no allocation). Zero at module load; the last-block
// ticket resets everything dirtied, so each graph replay starts identical.
__device__ int   g_done = 0;
__device__ float g_sum[16];
__device__ int   g_cnt[16];

__global__ void __launch_bounds__(NTHR)
k_all(const int* __restrict__ labels,
      const float* __restrict__ outputs_old,
      const float* __restrict__ features,
      const float* __restrict__ proto,
      const int* __restrict__ classes_old,
      const int* __restrict__ inc_step,
      float* __restrict__ out)
{
    const int tid  = threadIdx.x;
    const int lane = tid & 31;
    const int wid  = tid >> 5;            // 8 warps

    __shared__ float s_proto[16 * 257];   // padded rows; classes 0..15 reachable
    __shared__ float s_sum[16];
    __shared__ int   s_cnt[16];
    __shared__ unsigned char s_id[256];   // per-pixel pseudo-class (block-local)
    __shared__ unsigned short s_mask[16]; // per-segment active mask

    if (tid < 16) { s_sum[tid] = 0.0f; s_cnt[tid] = 0; }
    // stage prototypes (classes 0..15, vectorized)
    for (int i = tid; i < 16 * (CF / 4); i += NTHR) {
        int row = i >> 6, col4 = (i & 63) << 2;
        float4 v = reinterpret_cast<const float4*>(proto)[i];
        float* dst = s_proto + row * 257 + col4;
        dst[0] = v.x; dst[1] = v.y; dst[2] = v.z; dst[3] = v.w;
    }

    // ---- Phase 1: label gather + conditional 16-ch argmax (one pixel/thread) ----
    const int pix0 = blockIdx.x * 256;    // 256-aligned -> single b, aligned segments
    const int pix  = pix0 + tid;
    const int b    = pix >> 14;
    const int h    = (pix >> 7) & 127;
    const int w    = pix & 127;

    int lab = labels[(b * HL + 4 * h) * WL + 4 * w];   // nearest-down: src = 4*dst
    int id = 0;
    if (lab == 0) {
        const float* p = outputs_old
                       + (size_t)b * C_OLD * HL * WL
                       + (size_t)(4 * h) * WL + 4 * w;
        float best = p[0];
        #pragma unroll
        for (int c = 1; c < C_OLD; ++c) {
            float v = p[(size_t)c * HL * WL];
            if (v > best) { best = v; id = c; }        // strict > = first-max (jnp.argmax)
        }
    }
    s_id[tid] = (unsigned char)id;
    if (id) atomicAdd(&s_cnt[id], 1);

    unsigned m = __ballot_sync(0xffffffffu, id != 0);  // full warp, uniform trip count
    if (lane == 0)  s_mask[2 * wid]     = (unsigned short)(m & 0xffffu);
    if (lane == 16) s_mask[2 * wid + 1] = (unsigned short)(m >> 16);
    __syncthreads();

    // ---- Phase 2: warp per occupied segment; lane = channel stripe ----
    // Active pixels of a segment share the same 64B feature line per channel:
    // first pixel misses to DRAM, the rest hit L1.
    {
        const int hwb = pix0 & 16383;
        const float* fbase = features + (size_t)b * (CF * HW) + hwb;
        #pragma unroll
        for (int s = wid; s < 16; s += 8) {
            int mask = s_mask[s];
            if (!mask) continue;
            const float* fb = fbase + (s << 4);
            while (mask) {
                int j = __ffs(mask) - 1;
                mask &= mask - 1;
                int cid = s_id[(s << 4) + j];          // broadcast smem byte
                const float* pr = s_proto + cid * 257;

                float acc = 0.0f;
                #pragma unroll
                for (int k = 0; k < CF / 32; ++k) {
                    int c = lane + 32 * k;
                    float d = fb[c * HW + j] - pr[c];
                    acc += d * d;
                }
                #pragma unroll
                for (int o = 16; o; o >>= 1)
                    acc += __shfl_xor_sync(0xffffffffu, acc, o);
                if (lane == 0)
                    atomicAdd(&s_sum[cid], acc * (1.0f / CF));
            }
        }
    }
    __syncthreads();

    // ---- Flush block totals ----
    if (tid < 16) {
        if (s_cnt[tid])          atomicAdd(&g_cnt[tid], s_cnt[tid]);
        if (s_sum[tid] != 0.0f)  atomicAdd(&g_sum[tid], s_sum[tid]);
    }

    // ---- Non-spinning last-block ticket: finalize + scratch reset ----
    __threadfence();
    __syncthreads();
    __shared__ int s_ticket;
    if (tid == 0) s_ticket = atomicAdd(&g_done, 1);
    __syncthreads();
    if (s_ticket == NBLK - 1) {
        __threadfence();                  // all blocks' atomics now visible
        if (tid < 32) {
            int nc = *classes_old;
            if (nc > 16) nc = 16;
            float v = 0.0f;
            if (lane >= 1 && lane < nc && g_cnt[lane] > 0)
                v = g_sum[lane] / (float)g_cnt[lane];
            #pragma unroll
            for (int o = 16; o; o >>= 1)
                v += __shfl_xor_sync(0xffffffffu, v, o);
            if (lane == 0)
                out[0] = (*inc_step == 0) ? 0.0f : v;
        }
        __syncthreads();
        if (tid == 0) g_done = 0;
        if (tid < 16) { g_sum[tid] = 0.0f; g_cnt[tid] = 0; }
        __threadfence();
    }
}

extern "C" void kernel_launch(void* const* d_in, const int* in_sizes, int n_in,
                              void* d_out, int out_size) {
    // 0: outputs (unused)  1: outputs_old f32 [8,16,512,512]
    // 2: features f32 [8,256,128,128]  3: features_old (unused)
    // 4: labels i32 [8,512,512]  5: prototypes f32 [21,256]
    // 6: classes_old i32  7: incremental_step i32
    const float* outputs_old = (const float*)d_in[1];
    const float* features    = (const float*)d_in[2];
    const int*   labels      = (const int*)  d_in[4];
    const float* prototypes  = (const float*)d_in[5];
    const int*   classes_old = (const int*)  d_in[6];
    const int*   inc_step    = (const int*)  d_in[7];

    k_all<<<NBLK, NTHR>>>(labels, outputs_old, features, prototypes,
                          classes_old, inc_step, (float*)d_out);
}